// round 13
// baseline (speedup 1.0000x reference)
#include <cuda_runtime.h>
#include <cstddef>

// ---- problem constants ----
#define HH 384
#define WW 384
#define NPIX (HH*WW)          // 147456
#define BB 4
#define MM 192
#define NT 256
#define TILE_W 32
#define TILE_H 32
#define TILES_X (WW/TILE_W)            // 12
#define TILES_Y (HH/TILE_H)            // 12
#define NCHUNK (TILES_X*TILES_Y)       // 144
#define NBLK1 (BB*NCHUNK)              // 576
#define NBLK2 ((BB*MM)/8)              // 96 (8 warps/block, 1 warp per (b,j))
#define TOTBLK (NBLK1+NBLK2)           // 672 -> one wave @ 5 CTAs/SM
#define NWARP (NT/32)                  // 8
#define W2R 17                         // term2 fixed window side (17x17)
#define EPSF 1e-6f
#define MAX_DISTF 543.0580079975699f   // sqrt(384^2+384^2)
#define EPS_OVER_MAX 1.8414263e-9f     // 1e-6 / MAX_DIST
#define CMINR 0.999999f                // lower bound on c = 1/(p^4+eps')
#define BIGF 3.4e38f

// ---- scratch (static device globals; g_sem reset by finalizer) ----
__device__ float    g_t1part[NBLK1];
__device__ float    g_ppart [NBLK1];
__device__ float    g_jval  [BB*MM];
__device__ unsigned g_sem;

// ---- packed f32x2 helpers ----
__device__ __forceinline__ unsigned long long pk2(float a, float b) {
    unsigned long long r;
    asm("mov.b64 %0, {%1, %2};" : "=l"(r) : "f"(a), "f"(b));
    return r;
}
__device__ __forceinline__ void upk2(float& a, float& b, unsigned long long v) {
    asm("mov.b64 {%0, %1}, %2;" : "=f"(a), "=f"(b) : "l"(v));
}
__device__ __forceinline__ unsigned long long addx2(unsigned long long a, unsigned long long b) {
    unsigned long long r;
    asm("add.rn.f32x2 %0, %1, %2;" : "=l"(r) : "l"(a), "l"(b));
    return r;
}
__device__ __forceinline__ unsigned long long fmax2(unsigned long long a, unsigned long long b,
                                                    unsigned long long c) {
    unsigned long long r;
    asm("fma.rn.f32x2 %0, %1, %2, %3;" : "=l"(r) : "l"(a), "l"(b), "l"(c));
    return r;
}

__global__ __launch_bounds__(NT, 5)
void whd_all(const float* __restrict__ pm,
             const float* __restrict__ gt,
             const float* __restrict__ osz,
             float* __restrict__ out)
{
    __shared__ float2 s_gt[MM];        // (-gx_norm, -gy_norm) scaled, negated
    __shared__ float  s_red[NWARP*2];
    __shared__ float  s_t1[BB];
    __shared__ bool   s_last;

    const int tid  = threadIdx.x;
    const int lane = tid & 31;
    const int wid  = tid >> 5;
    const int bid  = blockIdx.x;

    if (bid < NBLK2) {
        // ==================== term2 role: one warp per (b,j) ====================
        // Maximize m = q*rsqrt(d2) over a CLAMPED 17x17 fully-in-image window:
        // compile-time row count -> 17 independent LDGs (one L2 round).
        // Exact when M*G*CMINR >= 1 (outside pixel value d*c >= G*CMINR).
        const int wg = bid * NWARP + wid;          // 0..767
        const int b  = wg / MM;
        const int j  = wg - b * MM;

        const float fy = osz[2*b+0] * (1.0f/(float)HH);
        const float fx = osz[2*b+1] * (1.0f/(float)WW);
        const float grow = gt[((size_t)b*MM + j)*2 + 0];
        const float gcol = gt[((size_t)b*MM + j)*2 + 1];
        const float* pmb = pm + (size_t)b * NPIX;

        const int cx = (int)gcol;
        const int cy = (int)grow;
        const int x0 = min(max(cx - W2R/2, 0), WW - W2R);   // clamp window inside image
        const int y0 = min(max(cy - W2R/2, 0), HH - W2R);

        float mmax = 0.f;
        if (lane < W2R) {
            const int px = x0 + lane;
            const float dxv = ((float)px - gcol) * fx;
            const float dx2 = dxv * dxv;
            const float* rowp = pmb + (size_t)y0 * WW + px;
            float dyv = ((float)y0 - grow) * fy;
#pragma unroll
            for (int yy = 0; yy < W2R; ++yy) {
                float p  = rowp[(size_t)yy * WW];            // independent loads, MLP~17
                float d2 = fmaf(dyv, dyv, dx2);
                dyv += fy;
                float pp = p*p;
                float q  = fmaf(pp, pp, EPS_OVER_MAX);       // p^4 + eps'
                mmax = fmaxf(mmax, q * rsqrtf(d2));
            }
        }
        unsigned u = __reduce_max_sync(0xffffffffu, __float_as_uint(mmax));
        float M = __uint_as_float(u);

        // certify: gap from GT to nearest pixel OUTSIDE the window (image sides: none)
        {
            const float GBIG = 1.0e18f;
            const int x1 = x0 + W2R - 1, y1 = y0 + W2R - 1;
            float gxl = (x0 == 0)    ? GBIG : (gcol - (float)x0 + 1.0f) * fx;
            float gxh = (x1 == WW-1) ? GBIG : ((float)x1 + 1.0f - gcol) * fx;
            float gyl = (y0 == 0)    ? GBIG : (grow - (float)y0 + 1.0f) * fy;
            float gyh = (y1 == HH-1) ? GBIG : ((float)y1 + 1.0f - grow) * fy;
            float G = fminf(fminf(gxl, gxh), fminf(gyl, gyh));
            if (!(M * G * CMINR >= 1.0f)) {
                // rare fallback: generic expanding scan (column strips)
                int r = 16;
                for (;;) {
                    int ex0 = cx - r, ex1 = cx + r, ey0 = cy - r, ey1 = cy + r;
                    const bool clx0 = (ex0 <= 0), clx1 = (ex1 >= WW-1);
                    const bool cly0 = (ey0 <= 0), cly1 = (ey1 >= HH-1);
                    ex0 = max(ex0, 0); ey0 = max(ey0, 0);
                    ex1 = min(ex1, WW-1); ey1 = min(ey1, HH-1);
                    float mm = 0.f;
                    for (int xs = ex0; xs <= ex1; xs += 32) {
                        int px = xs + lane;
                        if (px <= ex1) {
                            float dxv = ((float)px - gcol) * fx;
                            float dx2 = dxv * dxv;
                            const float* rowp = pmb + (size_t)ey0 * WW + px;
                            float dyv = ((float)ey0 - grow) * fy;
#pragma unroll 4
                            for (int y = ey0; y <= ey1; ++y) {
                                float p  = *rowp; rowp += WW;
                                float d2 = fmaf(dyv, dyv, dx2);
                                dyv += fy;
                                float pp = p*p;
                                float q  = fmaf(pp, pp, EPS_OVER_MAX);
                                mm = fmaxf(mm, q * rsqrtf(d2));
                            }
                        }
                    }
                    unsigned uu = __reduce_max_sync(0xffffffffu, __float_as_uint(mm));
                    M = __uint_as_float(uu);
                    if (clx0 && clx1 && cly0 && cly1) break;
                    float egxl = clx0 ? GBIG : (gcol - (float)ex0 + 1.0f) * fx;
                    float egxh = clx1 ? GBIG : ((float)ex1 + 1.0f - gcol) * fx;
                    float egyl = cly0 ? GBIG : (grow - (float)ey0 + 1.0f) * fy;
                    float egyh = cly1 ? GBIG : ((float)ey1 + 1.0f - grow) * fy;
                    float EG = fminf(fminf(egxl, egxh), fminf(egyl, egyh));
                    if (M * EG * CMINR >= 1.0f) break;
                    r <<= 1;
                }
            }
        }
        if (lane == 0)
            g_jval[wg] = fminf(__fdividef(1.0f, M), MAX_DISTF);  // min d*c, clipped
    } else {
        // ==================== term1 role: one 32x32 tile, warp-autonomous ====================
        const int tb    = bid - NBLK2;             // 0..575
        const int b     = tb / NCHUNK;
        const int chunk = tb - b * NCHUNK;
        const int tile_x = chunk % TILES_X;
        const int tile_y = chunk / TILES_X;

        const float* pmb = pm + (size_t)b * NPIX;
        const float* gtb = gt + (size_t)b * MM * 2;

        const int col0 = tile_x * TILE_W;
        const int row0 = tile_y * TILE_H;
        const int rowg = row0 + (tid >> 3);        // 32 rows x 8 runs
        const int colt = col0 + (tid & 7) * 4;     // 4 consecutive columns

        // ---- independent loads first ----
        const float4 pv = *reinterpret_cast<const float4*>(pmb + (size_t)rowg*WW + colt);
        const float fy = osz[2*b+0] * (1.0f/(float)HH);
        const float fx = osz[2*b+1] * (1.0f/(float)WW);

        // stage scaled, negated GT into smem (float4: two points per thread)
        if (tid < MM/2) {
            float4 gv = reinterpret_cast<const float4*>(gtb)[tid];  // {y0,x0,y1,x1}
            float4 sv;
            sv.x = -gv.y * fx;  sv.y = -gv.x * fy;                  // point 2*tid
            sv.z = -gv.w * fx;  sv.w = -gv.z * fy;                  // point 2*tid+1
            reinterpret_cast<float4*>(s_gt)[tid] = sv;
        }

        const float yn = (float)rowg * fy;
        const unsigned long long nx01 = pk2((float)(colt+0)*fx, (float)(colt+1)*fx);
        const unsigned long long nx23 = pk2((float)(colt+2)*fx, (float)(colt+3)*fx);

        const float cxn = ((float)col0 + 15.5f) * fx;
        const float cyn = ((float)row0 + 15.5f) * fy;
        const float hx = 15.5f * fx, hy = 15.5f * fy;
        const float Dh = sqrtf(hx*hx + hy*hy);     // tile half-diagonal

        __syncthreads();                            // sync #1: s_gt ready

        // ---- warp-private cull: each lane evaluates 6 points (j = 32g + lane) ----
        float dc2[6];
        float mn = BIGF;
#pragma unroll
        for (int g = 0; g < 6; ++g) {
            float2 gv = s_gt[g*32 + lane];
            float ax = gv.x + cxn;                 // -(gxn - cxn)
            float ay = gv.y + cyn;
            dc2[g] = fmaf(ax, ax, ay*ay);
            mn = fminf(mn, dc2[g]);
        }
        unsigned um = __reduce_min_sync(0xffffffffu, __float_as_uint(mn));
        float Uc = sqrtf(__uint_as_float(um));      // block-identical in every warp
        float thr = Uc + 2.0f*Dh + 1e-2f;
        float thr2 = thr * thr;

        // ---- hot loop: ballot + bit-scan -> indexed LDS broadcast ----
        unsigned long long dmn0 = pk2(BIGF, BIGF), dmn1 = pk2(BIGF, BIGF);
#pragma unroll
        for (int g = 0; g < 6; ++g) {
            unsigned ball = __ballot_sync(0xffffffffu, dc2[g] <= thr2);
            while (ball) {
                int src = __ffs(ball) - 1;
                ball &= ball - 1;
                float2 gv = s_gt[g*32 + src];       // LDS.64 broadcast
                float dy  = yn + gv.y;
                float dyy = dy * dy;
                unsigned long long dyy2 = pk2(dyy, dyy);
                unsigned long long gx2  = pk2(gv.x, gv.x);
                unsigned long long dx01 = addx2(nx01, gx2);
                unsigned long long d2a  = fmax2(dx01, dx01, dyy2);
                unsigned long long dx23 = addx2(nx23, gx2);
                unsigned long long d2b  = fmax2(dx23, dx23, dyy2);
                float a, bx, c, dd, m0, m1, m2, m3;
                upk2(a, bx, d2a); upk2(c, dd, d2b);
                upk2(m0, m1, dmn0); upk2(m2, m3, dmn1);
                dmn0 = pk2(fminf(m0, a), fminf(m1, bx));
                dmn1 = pk2(fminf(m2, c), fminf(m3, dd));
            }
        }

        // ---- term1 partial: sum p*sqrt(min d2), sum p ----
        float d0, d1, d2v, d3;
        upk2(d0, d1, dmn0); upk2(d2v, d3, dmn1);
        float t1 = pv.x*sqrtf(d0) + pv.y*sqrtf(d1) + pv.z*sqrtf(d2v) + pv.w*sqrtf(d3);
        float ps = pv.x + pv.y + pv.z + pv.w;
#pragma unroll
        for (int off = 16; off > 0; off >>= 1) {
            t1 += __shfl_down_sync(0xffffffffu, t1, off);
            ps += __shfl_down_sync(0xffffffffu, ps, off);
        }
        if (lane == 0) { s_red[wid] = t1; s_red[NWARP+wid] = ps; }
        __syncthreads();                            // sync #2
        if (wid == 0) {
            float tv  = (lane < NWARP) ? s_red[lane] : 0.f;
            float pv2 = (lane < NWARP) ? s_red[NWARP+lane] : 0.f;
#pragma unroll
            for (int off = 16; off > 0; off >>= 1) {
                tv  += __shfl_down_sync(0xffffffffu, tv,  off);
                pv2 += __shfl_down_sync(0xffffffffu, pv2, off);
            }
            if (lane == 0) { g_t1part[tb] = tv; g_ppart[tb] = pv2; }
        }
    }

    // ==================== common tail: last-block finalize ====================
    __threadfence();
    __syncthreads();
    if (tid == 0) s_last = (atomicAdd(&g_sem, 1u) == (unsigned)(TOTBLK - 1));
    __syncthreads();
    if (!s_last) return;

    // term2 total: fixed-order deterministic sum of 768 values
    float acc = 0.f;
#pragma unroll
    for (int t = tid; t < BB*MM; t += NT) acc += g_jval[t];
#pragma unroll
    for (int off = 16; off > 0; off >>= 1)
        acc += __shfl_down_sync(0xffffffffu, acc, off);

    // term1 ratios: warps 0..3, one image each (fixed-order)
    if (wid < BB) {
        float nu = 0.f, de = 0.f;
        for (int c = lane; c < NCHUNK; c += 32) {
            nu += g_t1part[wid*NCHUNK + c];
            de += g_ppart [wid*NCHUNK + c];
        }
#pragma unroll
        for (int off = 16; off > 0; off >>= 1) {
            nu += __shfl_down_sync(0xffffffffu, nu, off);
            de += __shfl_down_sync(0xffffffffu, de, off);
        }
        if (lane == 0) s_t1[wid] = nu / (de + EPSF);
    }
    if (lane == 0) s_red[wid] = acc;
    __syncthreads();

    if (tid == 0) {
        float t2 = 0.f;
#pragma unroll
        for (int w = 0; w < NWARP; ++w) t2 += s_red[w];
        float t1sum = 0.f;
#pragma unroll
        for (int bb = 0; bb < BB; ++bb) t1sum += s_t1[bb];
        out[0] = t1sum * (1.0f/(float)BB) + t2 * (1.0f/(float)(BB*MM));
        g_sem = 0u;                                // reset for next replay
    }
}

extern "C" void kernel_launch(void* const* d_in, const int* in_sizes, int n_in,
                              void* d_out, int out_size)
{
    const float* pm  = nullptr;
    const float* gt  = nullptr;
    const float* osz = nullptr;
    for (int i = 0; i < n_in; ++i) {
        if      (in_sizes[i] == BB*NPIX) pm  = (const float*)d_in[i];
        else if (in_sizes[i] == BB*MM*2) gt  = (const float*)d_in[i];
        else if (in_sizes[i] == BB*2)    osz = (const float*)d_in[i];
    }
    whd_all<<<TOTBLK, NT>>>(pm, gt, osz, (float*)d_out);
    (void)out_size;
}